// round 13
// baseline (speedup 1.0000x reference)
#include <cuda_runtime.h>
#include <math.h>
#include <stdint.h>

#define Bv   8
#define Hv   32
#define Wv   32
#define Lv   6
#define Rv   384
#define NHv  6
#define DHv  64
#define Mv   1365
#define NEv  2304
#define HIDv 9216
#define ROWSv (Bv*Hv*Wv*Lv)     /* 49152 */
#define BMv   (Bv*Mv)           /* 10920 */
#define MLPROWS (Bv*Hv*Wv)      /* 8192 */

// ---------------- scratch (static device globals; no allocation) ----------------
__device__ float g_uniq[Bv*Mv*Rv];
__device__ float g_qb  [Bv*Mv*Rv];
__device__ float g_kb  [Bv*Mv*Rv];
__device__ float g_vb  [Bv*Mv*Rv];
__device__ float g_ob  [Bv*Mv*Rv];
__device__ float g_attn[Bv*Mv*Rv];
__device__ float g_xres[ROWSv*Rv];
__device__ float g_flat[ROWSv*Rv];
__device__ float g_h1  [(size_t)MLPROWS*HIDv];
__device__ float g_w1t [(size_t)NEv*HIDv];   // transposed [HID][NE]
__device__ float g_w2t [(size_t)NEv*HIDv];   // transposed [NE][HID]
__device__ float g_wqt [Rv*Rv];              // transposed [N][K]
__device__ float g_wkt [Rv*Rv];
__device__ float g_wvt [Rv*Rv];
__device__ float g_wot [Rv*Rv];

__constant__ int c_off[6] = {0, 1024, 1280, 1344, 1360, 1364};

// ---------------- utility ----------------
__global__ void zero_kernel(float* p, int n) {
    int i = blockIdx.x * blockDim.x + threadIdx.x;
    int stride = gridDim.x * blockDim.x;
    for (; i < n; i += stride) p[i] = 0.f;
}

__device__ __forceinline__ float gelu_tanh(float v) {
    float u = 0.7978845608028654f * (v + 0.044715f * v * v * v);
    return 0.5f * v * (1.f + tanhf(u));
}

__device__ __forceinline__ uint32_t f2tf(float f) {
    uint32_t r;
    asm volatile("cvt.rna.tf32.f32 %0, %1;" : "=r"(r) : "f"(f));
    return r;
}
__device__ __forceinline__ float tfround(float f) { return __uint_as_float(f2tf(f)); }

__device__ __forceinline__ void cp_async16(uint32_t dst, const void* src, int sz) {
    asm volatile("cp.async.cg.shared.global [%0], [%1], 16, %2;\n"
                 :: "r"(dst), "l"(src), "r"(sz));
}
__device__ __forceinline__ void cp_commit() {
    asm volatile("cp.async.commit_group;\n");
}

__device__ __forceinline__ void ldsm4(uint32_t& r0, uint32_t& r1, uint32_t& r2, uint32_t& r3,
                                      uint32_t addr) {
    asm volatile("ldmatrix.sync.aligned.m8n8.x4.shared.b16 {%0,%1,%2,%3}, [%4];"
                 : "=r"(r0), "=r"(r1), "=r"(r2), "=r"(r3) : "r"(addr));
}

// elementwise tf32 rounding (vectorized, grid-stride). n % 4 == 0.
__global__ void tf32_round_kernel(float* __restrict__ dst, const float* __restrict__ src, int n) {
    int i = (blockIdx.x * blockDim.x + threadIdx.x) * 4;
    int stride = gridDim.x * blockDim.x * 4;
    for (; i < n; i += stride) {
        float4 v = *(const float4*)(src + i);
        v.x = tfround(v.x); v.y = tfround(v.y);
        v.z = tfround(v.z); v.w = tfround(v.w);
        *(float4*)(dst + i) = v;
    }
}

// transpose + tf32 round: src[K][N] -> dst[N][K]. K,N % 32 == 0. block (32,8).
__global__ __launch_bounds__(256) void transpose_tf32_kernel(
    float* __restrict__ dst, const float* __restrict__ src, int K, int N)
{
    __shared__ float tile[32][33];
    int k0 = blockIdx.y * 32, n0 = blockIdx.x * 32;
    int tx = threadIdx.x, ty = threadIdx.y;
    #pragma unroll
    for (int i = 0; i < 32; i += 8)
        tile[ty + i][tx] = src[(size_t)(k0 + ty + i) * N + n0 + tx];
    __syncthreads();
    #pragma unroll
    for (int i = 0; i < 32; i += 8)
        dst[(size_t)(n0 + ty + i) * K + k0 + tx] = tfround(tile[tx][ty + i]);
}

// ---------------- kernel 1: LN1 + segment-mean scatter into uniq ----------------
__global__ __launch_bounds__(128) void ln1_scatter_kernel(
    const float* __restrict__ x, const float* __restrict__ w, const float* __restrict__ bta)
{
    __shared__ float red[4];
    int row = blockIdx.x;
    int tid = threadIdx.x;
    int l = row % Lv;
    int t = row / Lv;
    int wc = t % Wv; t /= Wv;
    int hc = t % Hv;
    int b  = t / Hv;

    const float* xp = x + (size_t)row * Rv;
    float v0 = xp[tid], v1 = xp[tid + 128], v2 = xp[tid + 256];

    float s = v0 + v1 + v2;
    #pragma unroll
    for (int o = 16; o; o >>= 1) s += __shfl_down_sync(0xffffffffu, s, o);
    if ((tid & 31) == 0) red[tid >> 5] = s;
    __syncthreads();
    float mu = (red[0] + red[1] + red[2] + red[3]) * (1.f / Rv);
    __syncthreads();

    float d0 = v0 - mu, d1 = v1 - mu, d2 = v2 - mu;
    float sq = d0 * d0 + d1 * d1 + d2 * d2;
    #pragma unroll
    for (int o = 16; o; o >>= 1) sq += __shfl_down_sync(0xffffffffu, sq, o);
    if ((tid & 31) == 0) red[tid >> 5] = sq;
    __syncthreads();
    float var = (red[0] + red[1] + red[2] + red[3]) * (1.f / Rv);
    float rstd = rsqrtf(var + 1e-5f);

    int id = c_off[l] + (hc >> l) * (Wv >> l) + (wc >> l);
    float invc = 1.f / (float)(1 << (2 * l));
    float* up = g_uniq + ((size_t)b * Mv + id) * Rv;

    atomicAdd(up + tid,       (d0 * rstd * w[tid]       + bta[tid])       * invc);
    atomicAdd(up + tid + 128, (d1 * rstd * w[tid + 128] + bta[tid + 128]) * invc);
    atomicAdd(up + tid + 256, (d2 * rstd * w[tid + 256] + bta[tid + 256]) * invc);
}

// ---------------- kernel 2: TF32 mma.sync GEMM, 64x64 warp tiles, 2 CTAs/SM ------
// C(MxN) = A(MxK) @ Bt^T + bias, Bt layout [N][K], operands pre-rounded tf32.
// EPI 0: bias. EPI 1: gelu(bias+), tf32-rounded out. EPI 2: bias + residual.
// Block tile 128x128, K-tile 32, 3-stage cp.async, smem 110.6KB -> 2 CTAs/SM.
// 4 warps (grid 2x2), warp tile 64x64, mma.m16n8k8 tf32, 4x8 tiles/warp
// (128 acc regs). Per kk: 8 LDSM + 32 MMA -> A/B smem reads halved vs 8-warp grid.
// Requires: N % 128 == 0, K % 32 == 0. M arbitrary (guarded).
#define BMt 128
#define BNt 128
#define ASTRIDE 36               /* floats per A smem row (conflict-free LDSM) */
#define BSTN    36               /* floats per Bt smem row */
#define ASZ (BMt*ASTRIDE)        /* 4608 floats */
#define BSZ (BNt*BSTN)           /* 4608 floats */
#define STG (ASZ+BSZ)            /* 9216 floats per stage */
#define NSTAGE 3
#define GEMM_SMEM (NSTAGE*STG*4) /* 110592 bytes */

template<int EPI>
__global__ __launch_bounds__(128, 2) void tf32_gemm_kernel(
    int Mx, int Nx, int Kx,
    const float* __restrict__ A, const float* __restrict__ Bt,
    const float* __restrict__ bias, const float* __restrict__ res,
    float* __restrict__ C)
{
    extern __shared__ float sm[];

    int tid  = threadIdx.x;
    int lane = tid & 31;
    int warp = tid >> 5;     // 0..3
    int wm = warp >> 1;      // 0..1
    int wn = warp & 1;       // 0..1
    int lr = lane >> 2;      // 0..7
    int lc = lane & 3;       // 0..3

    int rowTile = blockIdx.y * BMt;
    int colTile = blockIdx.x * BNt;

    float acc[4][8][4];
    #pragma unroll
    for (int mt = 0; mt < 4; mt++)
        #pragma unroll
        for (int nt = 0; nt < 8; nt++)
            #pragma unroll
            for (int q = 0; q < 4; q++) acc[mt][nt][q] = 0.f;

    int KT = Kx >> 5;

    auto load_tile = [&](int kt, int st) {
        int k0 = kt << 5;
        float* As = sm + st * STG;
        float* Bs = As + ASZ;
        uint32_t sA = (uint32_t)__cvta_generic_to_shared(As);
        uint32_t sB = (uint32_t)__cvta_generic_to_shared(Bs);
        #pragma unroll
        for (int i = 0; i < 8; i++) {
            int idx = i * 128 + tid;            // 1024 chunks: 128 rows x 8
            int row = idx >> 3, c4 = (idx & 7) << 2;
            int gr = rowTile + row;
            const float* src = A + (size_t)(gr < Mx ? gr : (Mx - 1)) * Kx + k0 + c4;
            cp_async16(sA + (row * ASTRIDE + c4) * 4, src, gr < Mx ? 16 : 0);
        }
        #pragma unroll
        for (int i = 0; i < 8; i++) {
            int idx = i * 128 + tid;            // 1024 chunks: 128 n-rows x 8
            int row = idx >> 3, c4 = (idx & 7) << 2;
            cp_async16(sB + (row * BSTN + c4) * 4,
                       Bt + (size_t)(colTile + row) * Kx + k0 + c4, 16);
        }
        cp_commit();
    };

    load_tile(0, 0);
    if (KT > 1) load_tile(1, 1);

    // lane-dependent LDSM address components
    uint32_t aLane = ((wm * 64 + (lane & 15)) * ASTRIDE + ((lane & 16) ? 4 : 0)) * 4;
    uint32_t bLane = ((wn * 64 + (lane & 7) + ((lane & 16) ? 8 : 0)) * BSTN
                     + ((lane & 8) ? 4 : 0)) * 4;

    for (int kt = 0; kt < KT; kt++) {
        if (kt + 1 < KT) asm volatile("cp.async.wait_group 1;\n");
        else             asm volatile("cp.async.wait_group 0;\n");
        __syncthreads();
        if (kt + 2 < KT) load_tile(kt + 2, (kt + 2) % NSTAGE);

        const float* Ab = sm + (kt % NSTAGE) * STG;
        uint32_t aBase = (uint32_t)__cvta_generic_to_shared(Ab) + aLane;
        uint32_t bBase = (uint32_t)__cvta_generic_to_shared(Ab + ASZ) + bLane;

        #pragma unroll
        for (int kk = 0; kk < 4; kk++) {
            uint32_t af[4][4];
            uint32_t bf[8][2];
            #pragma unroll
            for (int mt = 0; mt < 4; mt++)
                ldsm4(af[mt][0], af[mt][1], af[mt][2], af[mt][3],
                      aBase + (mt * 16 * ASTRIDE + kk * 8) * 4);
            #pragma unroll
            for (int np = 0; np < 4; np++)
                ldsm4(bf[2 * np][0], bf[2 * np][1], bf[2 * np + 1][0], bf[2 * np + 1][1],
                      bBase + (np * 16 * BSTN + kk * 8) * 4);
            #pragma unroll
            for (int mt = 0; mt < 4; mt++)
                #pragma unroll
                for (int nt = 0; nt < 8; nt++) {
                    asm volatile(
                        "mma.sync.aligned.m16n8k8.row.col.f32.tf32.tf32.f32 "
                        "{%0,%1,%2,%3}, {%4,%5,%6,%7}, {%8,%9}, {%0,%1,%2,%3};\n"
                        : "+f"(acc[mt][nt][0]), "+f"(acc[mt][nt][1]),
                          "+f"(acc[mt][nt][2]), "+f"(acc[mt][nt][3])
                        : "r"(af[mt][0]), "r"(af[mt][1]), "r"(af[mt][2]), "r"(af[mt][3]),
                          "r"(bf[nt][0]), "r"(bf[nt][1]));
                }
        }
    }

    // ---- epilogue ----
    #pragma unroll
    for (int mt = 0; mt < 4; mt++) {
        #pragma unroll
        for (int nt = 0; nt < 8; nt++) {
            int r0 = rowTile + wm * 64 + mt * 16 + lr;
            int c0 = colTile + wn * 64 + nt * 8 + 2 * lc;
            #pragma unroll
            for (int q = 0; q < 4; q++) {
                int r = r0 + (q >> 1) * 8;
                int c = c0 + (q & 1);
                if (r < Mx) {
                    float val = acc[mt][nt][q] + bias[c];
                    if (EPI == 1) val = tfround(gelu_tanh(val));
                    if (EPI == 2) val += res[(size_t)r * Nx + c];
                    C[(size_t)r * Nx + c] = val;
                }
            }
        }
    }
}

// ---------------- kernel 3: attention over M=1365 nodes, flash-style ------------
#define AKT 64
__global__ __launch_bounds__(128) void attn_kernel()
{
    __shared__ float Ks[AKT][DHv];
    __shared__ float Vs[AKT][DHv];
    int b = blockIdx.z, h = blockIdx.y;
    int qm = blockIdx.x * 128 + threadIdx.x;
    bool valid = qm < Mv;
    int qsafe = valid ? qm : 0;

    const float* qptr = g_qb + ((size_t)(b * Mv + qsafe)) * Rv + h * DHv;
    float q[DHv];
    #pragma unroll
    for (int d = 0; d < DHv; d += 4) {
        float4 t = *(const float4*)(qptr + d);
        q[d] = t.x; q[d + 1] = t.y; q[d + 2] = t.z; q[d + 3] = t.w;
    }
    float o[DHv];
    #pragma unroll
    for (int d = 0; d < DHv; d++) o[d] = 0.f;
    float mmax = -1e30f, lsum = 0.f;

    for (int k0 = 0; k0 < Mv; k0 += AKT) {
        int nk = min(AKT, Mv - k0);
        __syncthreads();
        for (int idx = threadIdx.x; idx < AKT * (DHv / 4); idx += 128) {
            int j = idx >> 4, dq = (idx & 15) * 4;
            if (j < nk) {
                size_t base = ((size_t)(b * Mv + k0 + j)) * Rv + h * DHv + dq;
                *(float4*)&Ks[j][dq] = *(const float4*)(g_kb + base);
                *(float4*)&Vs[j][dq] = *(const float4*)(g_vb + base);
            }
        }
        __syncthreads();
        if (valid) {
            for (int j = 0; j < nk; j++) {
                const float4* kp = (const float4*)&Ks[j][0];
                float dot = 0.f;
                #pragma unroll
                for (int d4 = 0; d4 < DHv / 4; d4++) {
                    float4 kv = kp[d4];
                    dot = fmaf(q[4 * d4],     kv.x, dot);
                    dot = fmaf(q[4 * d4 + 1], kv.y, dot);
                    dot = fmaf(q[4 * d4 + 2], kv.z, dot);
                    dot = fmaf(q[4 * d4 + 3], kv.w, dot);
                }
                float s = dot * 0.125f;
                const float4* vp = (const float4*)&Vs[j][0];
                if (s <= mmax) {
                    float p = __expf(s - mmax);
                    lsum += p;
                    #pragma unroll
                    for (int d4 = 0; d4 < DHv / 4; d4++) {
                        float4 vv = vp[d4];
                        o[4 * d4]     = fmaf(p, vv.x, o[4 * d4]);
                        o[4 * d4 + 1] = fmaf(p, vv.y, o[4 * d4 + 1]);
                        o[4 * d4 + 2] = fmaf(p, vv.z, o[4 * d4 + 2]);
                        o[4 * d4 + 3] = fmaf(p, vv.w, o[4 * d4 + 3]);
                    }
                } else {
                    float alpha = __expf(mmax - s);
                    mmax = s;
                    lsum = lsum * alpha + 1.f;
                    #pragma unroll
                    for (int d4 = 0; d4 < DHv / 4; d4++) {
                        float4 vv = vp[d4];
                        o[4 * d4]     = fmaf(o[4 * d4],     alpha, vv.x);
                        o[4 * d4 + 1] = fmaf(o[4 * d4 + 1], alpha, vv.y);
                        o[4 * d4 + 2] = fmaf(o[4 * d4 + 2], alpha, vv.z);
                        o[4 * d4 + 3] = fmaf(o[4 * d4 + 3], alpha, vv.w);
                    }
                }
            }
        }
    }
    if (valid) {
        float inv = 1.f / lsum;
        float* op = g_ob + ((size_t)(b * Mv + qm)) * Rv + h * DHv;
        #pragma unroll
        for (int d = 0; d < DHv; d += 4) {
            float4 t = make_float4(tfround(o[d] * inv), tfround(o[d + 1] * inv),
                                   tfround(o[d + 2] * inv), tfround(o[d + 3] * inv));
            *(float4*)(op + d) = t;
        }
    }
}

// ---------------- kernel 4: gather + residual + LN2 -> x_res, flat --------------
__global__ __launch_bounds__(128) void res_ln2_kernel(
    const float* __restrict__ x, const float* __restrict__ w, const float* __restrict__ bta)
{
    __shared__ float red[4];
    int row = blockIdx.x;
    int tid = threadIdx.x;
    int l = row % Lv;
    int t = row / Lv;
    int wc = t % Wv; t /= Wv;
    int hc = t % Hv;
    int b  = t / Hv;

    int id = c_off[l] + (hc >> l) * (Wv >> l) + (wc >> l);
    const float* xp = x + (size_t)row * Rv;
    const float* ap = g_attn + ((size_t)b * Mv + id) * Rv;

    float v0 = xp[tid]       + ap[tid];
    float v1 = xp[tid + 128] + ap[tid + 128];
    float v2 = xp[tid + 256] + ap[tid + 256];

    float* rp = g_xres + (size_t)row * Rv;
    rp[tid] = v0; rp[tid + 128] = v1; rp[tid + 256] = v2;

    float s = v0 + v1 + v2;
    #pragma unroll
    for (int o = 16; o; o >>= 1) s += __shfl_down_sync(0xffffffffu, s, o);
    if ((tid & 31) == 0) red[tid >> 5] = s;
    __syncthreads();
    float mu = (red[0] + red[1] + red[2] + red[3]) * (1.f / Rv);
    __syncthreads();

    float d0 = v0 - mu, d1 = v1 - mu, d2 = v2 - mu;
    float sq = d0 * d0 + d1 * d1 + d2 * d2;
    #pragma unroll
    for (int o = 16; o; o >>= 1) sq += __shfl_down_sync(0xffffffffu, sq, o);
    if ((tid & 31) == 0) red[tid >> 5] = sq;
    __syncthreads();
    float var = (red[0] + red[1] + red[2] + red[3]) * (1.f / Rv);
    float rstd = rsqrtf(var + 1e-5f);

    float* fp = g_flat + (size_t)row * Rv;  // tf32-rounded: feeds MLP GEMM1
    fp[tid]       = tfround(d0 * rstd * w[tid]       + bta[tid]);
    fp[tid + 128] = tfround(d1 * rstd * w[tid + 128] + bta[tid + 128]);
    fp[tid + 256] = tfround(d2 * rstd * w[tid + 256] + bta[tid + 256]);
}

// ---------------- launch ----------------
extern "C" void kernel_launch(void* const* d_in, const int* in_sizes, int n_in,
                              void* d_out, int out_size) {
    const float* x    = (const float*)d_in[0];
    const float* ln1w = (const float*)d_in[1];
    const float* ln1b = (const float*)d_in[2];
    const float* ln2w = (const float*)d_in[3];
    const float* ln2b = (const float*)d_in[4];
    const float* wq = (const float*)d_in[5];  const float* bq = (const float*)d_in[6];
    const float* wk = (const float*)d_in[7];  const float* bk = (const float*)d_in[8];
    const float* wv = (const float*)d_in[9];  const float* bv = (const float*)d_in[10];
    const float* wo = (const float*)d_in[11]; const float* bo = (const float*)d_in[12];
    const float* w1 = (const float*)d_in[13]; const float* b1 = (const float*)d_in[14];
    const float* w2 = (const float*)d_in[15]; const float* b2 = (const float*)d_in[16];
    float* out = (float*)d_out;

    float *uniq, *qb, *kb, *vb, *ob, *attn, *xres, *flat, *h1;
    float *w1t, *w2t, *wqt, *wkt, *wvt, *wot;
    cudaGetSymbolAddress((void**)&uniq, g_uniq);
    cudaGetSymbolAddress((void**)&qb,   g_qb);
    cudaGetSymbolAddress((void**)&kb,   g_kb);
    cudaGetSymbolAddress((void**)&vb,   g_vb);
    cudaGetSymbolAddress((void**)&ob,   g_ob);
    cudaGetSymbolAddress((void**)&attn, g_attn);
    cudaGetSymbolAddress((void**)&xres, g_xres);
    cudaGetSymbolAddress((void**)&flat, g_flat);
    cudaGetSymbolAddress((void**)&h1,   g_h1);
    cudaGetSymbolAddress((void**)&w1t,  g_w1t);
    cudaGetSymbolAddress((void**)&w2t,  g_w2t);
    cudaGetSymbolAddress((void**)&wqt,  g_wqt);
    cudaGetSymbolAddress((void**)&wkt,  g_wkt);
    cudaGetSymbolAddress((void**)&wvt,  g_wvt);
    cudaGetSymbolAddress((void**)&wot,  g_wot);

    cudaFuncSetAttribute(tf32_gemm_kernel<0>, cudaFuncAttributeMaxDynamicSharedMemorySize, GEMM_SMEM);
    cudaFuncSetAttribute(tf32_gemm_kernel<1>, cudaFuncAttributeMaxDynamicSharedMemorySize, GEMM_SMEM);
    cudaFuncSetAttribute(tf32_gemm_kernel<2>, cudaFuncAttributeMaxDynamicSharedMemorySize, GEMM_SMEM);

    // 0. transpose + tf32-round all weights into scratch copies ([N][K] layout)
    transpose_tf32_kernel<<<dim3(HIDv / 32, NEv / 32),  dim3(32, 8)>>>(w1t, w1, NEv, HIDv);
    transpose_tf32_kernel<<<dim3(NEv / 32,  HIDv / 32), dim3(32, 8)>>>(w2t, w2, HIDv, NEv);
    transpose_tf32_kernel<<<dim3(Rv / 32, Rv / 32), dim3(32, 8)>>>(wqt, wq, Rv, Rv);
    transpose_tf32_kernel<<<dim3(Rv / 32, Rv / 32), dim3(32, 8)>>>(wkt, wk, Rv, Rv);
    transpose_tf32_kernel<<<dim3(Rv / 32, Rv / 32), dim3(32, 8)>>>(wvt, wv, Rv, Rv);
    transpose_tf32_kernel<<<dim3(Rv / 32, Rv / 32), dim3(32, 8)>>>(wot, wo, Rv, Rv);

    // 1. zero uniq accumulator
    zero_kernel<<<4096, 256>>>(uniq, Bv * Mv * Rv);
    // 2. LN1 + segment-mean scatter
    ln1_scatter_kernel<<<ROWSv, 128>>>(x, ln1w, ln1b);
    // 2b. round uniq in place (feeds QKV GEMMs)
    tf32_round_kernel<<<2048, 256>>>(uniq, uniq, Bv * Mv * Rv);
    // 3-5. Q/K/V projections: (10920 x 384) @ (384 x 384)
    dim3 gq(Rv / BNt, (BMv + BMt - 1) / BMt);
    tf32_gemm_kernel<0><<<gq, 128, GEMM_SMEM>>>(BMv, Rv, Rv, uniq, wqt, bq, nullptr, qb);
    tf32_gemm_kernel<0><<<gq, 128, GEMM_SMEM>>>(BMv, Rv, Rv, uniq, wkt, bk, nullptr, kb);
    tf32_gemm_kernel<0><<<gq, 128, GEMM_SMEM>>>(BMv, Rv, Rv, uniq, wvt, bv, nullptr, vb);
    // 6. attention over the 1365 tree nodes (stores tf32-rounded ob)
    attn_kernel<<<dim3((Mv + 127) / 128, NHv, Bv), 128>>>();
    // 7. output projection
    tf32_gemm_kernel<0><<<gq, 128, GEMM_SMEM>>>(BMv, Rv, Rv, ob, wot, bo, nullptr, attn);
    // 8. gather + residual + LN2 (stores tf32-rounded flat)
    res_ln2_kernel<<<ROWSv, 128>>>(x, ln2w, ln2b);
    // 9. MLP GEMM1 + GELU (rounds h1): (8192 x 2304) @ (2304 x 9216)
    tf32_gemm_kernel<1><<<dim3(HIDv / BNt, MLPROWS / BMt), 128, GEMM_SMEM>>>(MLPROWS, HIDv, NEv, flat, w1t, b1, nullptr, h1);
    // 10. MLP GEMM2 + bias + residual -> d_out: (8192 x 9216) @ (9216 x 2304)
    tf32_gemm_kernel<2><<<dim3(NEv / BNt, MLPROWS / BMt), 128, GEMM_SMEM>>>(MLPROWS, NEv, HIDv, h1, w2t, b2, xres, out);
}

// round 14
// speedup vs baseline: 1.0248x; 1.0248x over previous
#include <cuda_runtime.h>
#include <math.h>
#include <stdint.h>

#define Bv   8
#define Hv   32
#define Wv   32
#define Lv   6
#define Rv   384
#define NHv  6
#define DHv  64
#define Mv   1365
#define NEv  2304
#define HIDv 9216
#define QKVN 1152               /* fused QKV output width */
#define ROWSv (Bv*Hv*Wv*Lv)     /* 49152 */
#define BMv   (Bv*Mv)           /* 10920 */
#define MLPROWS (Bv*Hv*Wv)      /* 8192 */

// ---------------- scratch (static device globals; no allocation) ----------------
__device__ float g_uniq[Bv*Mv*Rv];
__device__ float g_qkv [(size_t)BMv*QKVN];   // fused Q|K|V, row stride 1152
__device__ float g_bqkv[QKVN];               // concat bias bq|bk|bv
__device__ float g_ob  [Bv*Mv*Rv];
__device__ float g_attn[Bv*Mv*Rv];
__device__ float g_xres[ROWSv*Rv];
__device__ float g_flat[ROWSv*Rv];
__device__ float g_h1  [(size_t)MLPROWS*HIDv];
__device__ float g_w1t [(size_t)NEv*HIDv];   // transposed [HID][NE]
__device__ float g_w2t [(size_t)NEv*HIDv];   // transposed [NE][HID]
__device__ float g_wqkvt[QKVN*Rv];           // transposed concat [1152][384]
__device__ float g_wot [Rv*Rv];              // transposed [N][K]

__constant__ int c_off[6] = {0, 1024, 1280, 1344, 1360, 1364};

// ---------------- utility ----------------
__device__ __forceinline__ float gelu_tanh(float v) {
    float u = 0.7978845608028654f * (v + 0.044715f * v * v * v);
    return 0.5f * v * (1.f + tanhf(u));
}

__device__ __forceinline__ uint32_t f2tf(float f) {
    uint32_t r;
    asm volatile("cvt.rna.tf32.f32 %0, %1;" : "=r"(r) : "f"(f));
    return r;
}
__device__ __forceinline__ float tfround(float f) { return __uint_as_float(f2tf(f)); }

// zero uniq + build concat QKV bias
__global__ void zero_kernel(float* p, int n,
                            float* bqkv, const float* bq, const float* bk, const float* bv) {
    int g = blockIdx.x * blockDim.x + threadIdx.x;
    if (g < QKVN)
        bqkv[g] = (g < Rv) ? bq[g] : (g < 2 * Rv) ? bk[g - Rv] : bv[g - 2 * Rv];
    int stride = gridDim.x * blockDim.x;
    for (int i = g; i < n; i += stride) p[i] = 0.f;
}

__device__ __forceinline__ void cp_async16(uint32_t dst, const void* src, int sz) {
    asm volatile("cp.async.cg.shared.global [%0], [%1], 16, %2;\n"
                 :: "r"(dst), "l"(src), "r"(sz));
}
__device__ __forceinline__ void cp_commit() {
    asm volatile("cp.async.commit_group;\n");
}

__device__ __forceinline__ void ldsm4(uint32_t& r0, uint32_t& r1, uint32_t& r2, uint32_t& r3,
                                      uint32_t addr) {
    asm volatile("ldmatrix.sync.aligned.m8n8.x4.shared.b16 {%0,%1,%2,%3}, [%4];"
                 : "=r"(r0), "=r"(r1), "=r"(r2), "=r"(r3) : "r"(addr));
}

// elementwise tf32 rounding (vectorized, grid-stride). n % 4 == 0.
__global__ void tf32_round_kernel(float* __restrict__ dst, const float* __restrict__ src, int n) {
    int i = (blockIdx.x * blockDim.x + threadIdx.x) * 4;
    int stride = gridDim.x * blockDim.x * 4;
    for (; i < n; i += stride) {
        float4 v = *(const float4*)(src + i);
        v.x = tfround(v.x); v.y = tfround(v.y);
        v.z = tfround(v.z); v.w = tfround(v.w);
        *(float4*)(dst + i) = v;
    }
}

// transpose + tf32 round: src[K][N] -> dst[N][K]. K,N % 32 == 0. block (32,8).
__global__ __launch_bounds__(256) void transpose_tf32_kernel(
    float* __restrict__ dst, const float* __restrict__ src, int K, int N)
{
    __shared__ float tile[32][33];
    int k0 = blockIdx.y * 32, n0 = blockIdx.x * 32;
    int tx = threadIdx.x, ty = threadIdx.y;
    #pragma unroll
    for (int i = 0; i < 32; i += 8)
        tile[ty + i][tx] = src[(size_t)(k0 + ty + i) * N + n0 + tx];
    __syncthreads();
    #pragma unroll
    for (int i = 0; i < 32; i += 8)
        dst[(size_t)(n0 + ty + i) * K + k0 + tx] = tfround(tile[tx][ty + i]);
}

// fused transpose of wq|wk|wv into g_wqkvt [1152][384]; grid.z selects source
__global__ __launch_bounds__(256) void transpose_qkv_kernel(
    float* __restrict__ dstAll,
    const float* __restrict__ wq, const float* __restrict__ wk, const float* __restrict__ wv)
{
    __shared__ float tile[32][33];
    const float* src = (blockIdx.z == 0) ? wq : (blockIdx.z == 1) ? wk : wv;
    float* dst = dstAll + (size_t)blockIdx.z * Rv * Rv;
    int k0 = blockIdx.y * 32, n0 = blockIdx.x * 32;
    int tx = threadIdx.x, ty = threadIdx.y;
    #pragma unroll
    for (int i = 0; i < 32; i += 8)
        tile[ty + i][tx] = src[(size_t)(k0 + ty + i) * Rv + n0 + tx];
    __syncthreads();
    #pragma unroll
    for (int i = 0; i < 32; i += 8)
        dst[(size_t)(n0 + ty + i) * Rv + k0 + tx] = tfround(tile[tx][ty + i]);
}

// ---------------- kernel 1: LN1 + segment-mean scatter into uniq ----------------
__global__ __launch_bounds__(128) void ln1_scatter_kernel(
    const float* __restrict__ x, const float* __restrict__ w, const float* __restrict__ bta)
{
    __shared__ float red[4];
    int row = blockIdx.x;
    int tid = threadIdx.x;
    int l = row % Lv;
    int t = row / Lv;
    int wc = t % Wv; t /= Wv;
    int hc = t % Hv;
    int b  = t / Hv;

    const float* xp = x + (size_t)row * Rv;
    float v0 = xp[tid], v1 = xp[tid + 128], v2 = xp[tid + 256];

    float s = v0 + v1 + v2;
    #pragma unroll
    for (int o = 16; o; o >>= 1) s += __shfl_down_sync(0xffffffffu, s, o);
    if ((tid & 31) == 0) red[tid >> 5] = s;
    __syncthreads();
    float mu = (red[0] + red[1] + red[2] + red[3]) * (1.f / Rv);
    __syncthreads();

    float d0 = v0 - mu, d1 = v1 - mu, d2 = v2 - mu;
    float sq = d0 * d0 + d1 * d1 + d2 * d2;
    #pragma unroll
    for (int o = 16; o; o >>= 1) sq += __shfl_down_sync(0xffffffffu, sq, o);
    if ((tid & 31) == 0) red[tid >> 5] = sq;
    __syncthreads();
    float var = (red[0] + red[1] + red[2] + red[3]) * (1.f / Rv);
    float rstd = rsqrtf(var + 1e-5f);

    int id = c_off[l] + (hc >> l) * (Wv >> l) + (wc >> l);
    float invc = 1.f / (float)(1 << (2 * l));
    float* up = g_uniq + ((size_t)b * Mv + id) * Rv;

    atomicAdd(up + tid,       (d0 * rstd * w[tid]       + bta[tid])       * invc);
    atomicAdd(up + tid + 128, (d1 * rstd * w[tid + 128] + bta[tid + 128]) * invc);
    atomicAdd(up + tid + 256, (d2 * rstd * w[tid + 256] + bta[tid + 256]) * invc);
}

// ---------------- kernel 2: TF32 mma.sync GEMM (R6 champion config) --------------
// C(MxN) = A(MxK) @ Bt^T + bias, Bt layout [N][K], operands pre-rounded tf32.
// EPI 0: bias. EPI 1: gelu(bias+), tf32-rounded out. EPI 2: bias + residual.
// Block tile 128x128, K-tile 32, 3-stage cp.async, smem 110.6KB -> 2 CTAs/SM.
// 8 warps (grid 2x4), warp tile 64x32, mma.m16n8k8 tf32, 4x4 tiles/warp.
// Requires: N % 128 == 0, K % 32 == 0. M arbitrary (guarded).
#define BMt 128
#define BNt 128
#define ASTRIDE 36               /* floats per A smem row (conflict-free LDSM) */
#define BSTN    36               /* floats per Bt smem row */
#define ASZ (BMt*ASTRIDE)        /* 4608 floats */
#define BSZ (BNt*BSTN)           /* 4608 floats */
#define STG (ASZ+BSZ)            /* 9216 floats per stage */
#define NSTAGE 3
#define GEMM_SMEM (NSTAGE*STG*4) /* 110592 bytes */

template<int EPI>
__global__ __launch_bounds__(256, 2) void tf32_gemm_kernel(
    int Mx, int Nx, int Kx,
    const float* __restrict__ A, const float* __restrict__ Bt,
    const float* __restrict__ bias, const float* __restrict__ res,
    float* __restrict__ C)
{
    extern __shared__ float sm[];

    int tid  = threadIdx.x;
    int lane = tid & 31;
    int warp = tid >> 5;
    int wm = warp >> 2;     // 0..1
    int wn = warp & 3;      // 0..3
    int lr = lane >> 2;     // 0..7
    int lc = lane & 3;      // 0..3

    int rowTile = blockIdx.y * BMt;
    int colTile = blockIdx.x * BNt;

    float acc[4][4][4];
    #pragma unroll
    for (int mt = 0; mt < 4; mt++)
        #pragma unroll
        for (int nt = 0; nt < 4; nt++)
            #pragma unroll
            for (int q = 0; q < 4; q++) acc[mt][nt][q] = 0.f;

    int KT = Kx >> 5;

    auto load_tile = [&](int kt, int st) {
        int k0 = kt << 5;
        float* As = sm + st * STG;
        float* Bs = As + ASZ;
        uint32_t sA = (uint32_t)__cvta_generic_to_shared(As);
        uint32_t sB = (uint32_t)__cvta_generic_to_shared(Bs);
        #pragma unroll
        for (int i = 0; i < 4; i++) {
            int idx = i * 256 + tid;            // 1024 chunks: 128 rows x 8
            int row = idx >> 3, c4 = (idx & 7) << 2;
            int gr = rowTile + row;
            const float* src = A + (size_t)(gr < Mx ? gr : (Mx - 1)) * Kx + k0 + c4;
            cp_async16(sA + (row * ASTRIDE + c4) * 4, src, gr < Mx ? 16 : 0);
        }
        #pragma unroll
        for (int i = 0; i < 4; i++) {
            int idx = i * 256 + tid;            // 1024 chunks: 128 n-rows x 8
            int row = idx >> 3, c4 = (idx & 7) << 2;
            cp_async16(sB + (row * BSTN + c4) * 4,
                       Bt + (size_t)(colTile + row) * Kx + k0 + c4, 16);
        }
        cp_commit();
    };

    load_tile(0, 0);
    if (KT > 1) load_tile(1, 1);

    // lane-dependent LDSM address components
    uint32_t aLane = ((wm * 64 + (lane & 15)) * ASTRIDE + ((lane & 16) ? 4 : 0)) * 4;
    uint32_t bLane = ((wn * 32 + (lane & 7) + ((lane & 16) ? 8 : 0)) * BSTN
                     + ((lane & 8) ? 4 : 0)) * 4;

    for (int kt = 0; kt < KT; kt++) {
        if (kt + 1 < KT) asm volatile("cp.async.wait_group 1;\n");
        else             asm volatile("cp.async.wait_group 0;\n");
        __syncthreads();
        if (kt + 2 < KT) load_tile(kt + 2, (kt + 2) % NSTAGE);

        const float* Ab = sm + (kt % NSTAGE) * STG;
        uint32_t aBase = (uint32_t)__cvta_generic_to_shared(Ab) + aLane;
        uint32_t bBase = (uint32_t)__cvta_generic_to_shared(Ab + ASZ) + bLane;

        #pragma unroll
        for (int kk = 0; kk < 4; kk++) {
            uint32_t af[4][4];
            uint32_t bf[4][2];
            #pragma unroll
            for (int mt = 0; mt < 4; mt++)
                ldsm4(af[mt][0], af[mt][1], af[mt][2], af[mt][3],
                      aBase + (mt * 16 * ASTRIDE + kk * 8) * 4);
            #pragma unroll
            for (int np = 0; np < 2; np++)
                ldsm4(bf[2 * np][0], bf[2 * np][1], bf[2 * np + 1][0], bf[2 * np + 1][1],
                      bBase + (np * 16 * BSTN + kk * 8) * 4);
            #pragma unroll
            for (int mt = 0; mt < 4; mt++)
                #pragma unroll
                for (int nt = 0; nt < 4; nt++) {
                    asm volatile(
                        "mma.sync.aligned.m16n8k8.row.col.f32.tf32.tf32.f32 "
                        "{%0,%1,%2,%3}, {%4,%5,%6,%7}, {%8,%9}, {%0,%1,%2,%3};\n"
                        : "+f"(acc[mt][nt][0]), "+f"(acc[mt][nt][1]),
                          "+f"(acc[mt][nt][2]), "+f"(acc[mt][nt][3])
                        : "r"(af[mt][0]), "r"(af[mt][1]), "r"(af[mt][2]), "r"(af[mt][3]),
                          "r"(bf[nt][0]), "r"(bf[nt][1]));
                }
        }
    }

    // ---- epilogue ----
    #pragma unroll
    for (int mt = 0; mt < 4; mt++) {
        #pragma unroll
        for (int nt = 0; nt < 4; nt++) {
            int r0 = rowTile + wm * 64 + mt * 16 + lr;
            int c0 = colTile + wn * 32 + nt * 8 + 2 * lc;
            #pragma unroll
            for (int q = 0; q < 4; q++) {
                int r = r0 + (q >> 1) * 8;
                int c = c0 + (q & 1);
                if (r < Mx) {
                    float val = acc[mt][nt][q] + bias[c];
                    if (EPI == 1) val = tfround(gelu_tanh(val));
                    if (EPI == 2) val += res[(size_t)r * Nx + c];
                    C[(size_t)r * Nx + c] = val;
                }
            }
        }
    }
}

// ---------------- kernel 3: attention over M=1365 nodes, flash-style ------------
// reads fused g_qkv: Q at +0, K at +384, V at +768 within each 1152-float row
#define AKT 64
__global__ __launch_bounds__(128) void attn_kernel()
{
    __shared__ float Ks[AKT][DHv];
    __shared__ float Vs[AKT][DHv];
    int b = blockIdx.z, h = blockIdx.y;
    int qm = blockIdx.x * 128 + threadIdx.x;
    bool valid = qm < Mv;
    int qsafe = valid ? qm : 0;

    const float* qptr = g_qkv + (size_t)(b * Mv + qsafe) * QKVN + h * DHv;
    float q[DHv];
    #pragma unroll
    for (int d = 0; d < DHv; d += 4) {
        float4 t = *(const float4*)(qptr + d);
        q[d] = t.x; q[d + 1] = t.y; q[d + 2] = t.z; q[d + 3] = t.w;
    }
    float o[DHv];
    #pragma unroll
    for (int d = 0; d < DHv; d++) o[d] = 0.f;
    float mmax = -1e30f, lsum = 0.f;

    for (int k0 = 0; k0 < Mv; k0 += AKT) {
        int nk = min(AKT, Mv - k0);
        __syncthreads();
        for (int idx = threadIdx.x; idx < AKT * (DHv / 4); idx += 128) {
            int j = idx >> 4, dq = (idx & 15) * 4;
            if (j < nk) {
                size_t rowb = (size_t)(b * Mv + k0 + j) * QKVN + h * DHv + dq;
                *(float4*)&Ks[j][dq] = *(const float4*)(g_qkv + rowb + Rv);
                *(float4*)&Vs[j][dq] = *(const float4*)(g_qkv + rowb + 2 * Rv);
            }
        }
        __syncthreads();
        if (valid) {
            for (int j = 0; j < nk; j++) {
                const float4* kp = (const float4*)&Ks[j][0];
                float dot = 0.f;
                #pragma unroll
                for (int d4 = 0; d4 < DHv / 4; d4++) {
                    float4 kv = kp[d4];
                    dot = fmaf(q[4 * d4],     kv.x, dot);
                    dot = fmaf(q[4 * d4 + 1], kv.y, dot);
                    dot = fmaf(q[4 * d4 + 2], kv.z, dot);
                    dot = fmaf(q[4 * d4 + 3], kv.w, dot);
                }
                float s = dot * 0.125f;
                const float4* vp = (const float4*)&Vs[j][0];
                if (s <= mmax) {
                    float p = __expf(s - mmax);
                    lsum += p;
                    #pragma unroll
                    for (int d4 = 0; d4 < DHv / 4; d4++) {
                        float4 vv = vp[d4];
                        o[4 * d4]     = fmaf(p, vv.x, o[4 * d4]);
                        o[4 * d4 + 1] = fmaf(p, vv.y, o[4 * d4 + 1]);
                        o[4 * d4 + 2] = fmaf(p, vv.z, o[4 * d4 + 2]);
                        o[4 * d4 + 3] = fmaf(p, vv.w, o[4 * d4 + 3]);
                    }
                } else {
                    float alpha = __expf(mmax - s);
                    mmax = s;
                    lsum = lsum * alpha + 1.f;
                    #pragma unroll
                    for (int d4 = 0; d4 < DHv / 4; d4++) {
                        float4 vv = vp[d4];
                        o[4 * d4]     = fmaf(o[4 * d4],     alpha, vv.x);
                        o[4 * d4 + 1] = fmaf(o[4 * d4 + 1], alpha, vv.y);
                        o[4 * d4 + 2] = fmaf(o[4 * d4 + 2], alpha, vv.z);
                        o[4 * d4 + 3] = fmaf(o[4 * d4 + 3], alpha, vv.w);
                    }
                }
            }
        }
    }
    if (valid) {
        float inv = 1.f / lsum;
        float* op = g_ob + (size_t)(b * Mv + qm) * Rv + h * DHv;
        #pragma unroll
        for (int d = 0; d < DHv; d += 4) {
            float4 t = make_float4(tfround(o[d] * inv), tfround(o[d + 1] * inv),
                                   tfround(o[d + 2] * inv), tfround(o[d + 3] * inv));
            *(float4*)(op + d) = t;
        }
    }
}

// ---------------- kernel 4: gather + residual + LN2 -> x_res, flat --------------
__global__ __launch_bounds__(128) void res_ln2_kernel(
    const float* __restrict__ x, const float* __restrict__ w, const float* __restrict__ bta)
{
    __shared__ float red[4];
    int row = blockIdx.x;
    int tid = threadIdx.x;
    int l = row % Lv;
    int t = row / Lv;
    int wc = t % Wv; t /= Wv;
    int hc = t % Hv;
    int b  = t / Hv;

    int id = c_off[l] + (hc >> l) * (Wv >> l) + (wc >> l);
    const float* xp = x + (size_t)row * Rv;
    const float* ap = g_attn + ((size_t)b * Mv + id) * Rv;

    float v0 = xp[tid]       + ap[tid];
    float v1 = xp[tid + 128] + ap[tid + 128];
    float v2 = xp[tid + 256] + ap[tid + 256];

    float* rp = g_xres + (size_t)row * Rv;
    rp[tid] = v0; rp[tid + 128] = v1; rp[tid + 256] = v2;

    float s = v0 + v1 + v2;
    #pragma unroll
    for (int o = 16; o; o >>= 1) s += __shfl_down_sync(0xffffffffu, s, o);
    if ((tid & 31) == 0) red[tid >> 5] = s;
    __syncthreads();
    float mu = (red[0] + red[1] + red[2] + red[3]) * (1.f / Rv);
    __syncthreads();

    float d0 = v0 - mu, d1 = v1 - mu, d2 = v2 - mu;
    float sq = d0 * d0 + d1 * d1 + d2 * d2;
    #pragma unroll
    for (int o = 16; o; o >>= 1) sq += __shfl_down_sync(0xffffffffu, sq, o);
    if ((tid & 31) == 0) red[tid >> 5] = sq;
    __syncthreads();
    float var = (red[0] + red[1] + red[2] + red[3]) * (1.f / Rv);
    float rstd = rsqrtf(var + 1e-5f);

    float* fp = g_flat + (size_t)row * Rv;  // tf32-rounded: feeds MLP GEMM1
    fp[tid]       = tfround(d0 * rstd * w[tid]       + bta[tid]);
    fp[tid + 128] = tfround(d1 * rstd * w[tid + 128] + bta[tid + 128]);
    fp[tid + 256] = tfround(d2 * rstd * w[tid + 256] + bta[tid + 256]);
}

// ---------------- launch ----------------
extern "C" void kernel_launch(void* const* d_in, const int* in_sizes, int n_in,
                              void* d_out, int out_size) {
    const float* x    = (const float*)d_in[0];
    const float* ln1w = (const float*)d_in[1];
    const float* ln1b = (const float*)d_in[2];
    const float* ln2w = (const float*)d_in[3];
    const float* ln2b = (const float*)d_in[4];
    const float* wq = (const float*)d_in[5];  const float* bq = (const float*)d_in[6];
    const float* wk = (const float*)d_in[7];  const float* bk = (const float*)d_in[8];
    const float* wv = (const float*)d_in[9];  const float* bv = (const float*)d_in[10];
    const float* wo = (const float*)d_in[11]; const float* bo = (const float*)d_in[12];
    const float* w1 = (const float*)d_in[13]; const float* b1 = (const float*)d_in[14];
    const float* w2 = (const float*)d_in[15]; const float* b2 = (const float*)d_in[16];
    float* out = (float*)d_out;

    float *uniq, *qkv, *bqkv, *ob, *attn, *xres, *flat, *h1;
    float *w1t, *w2t, *wqkvt, *wot;
    cudaGetSymbolAddress((void**)&uniq,  g_uniq);
    cudaGetSymbolAddress((void**)&qkv,   g_qkv);
    cudaGetSymbolAddress((void**)&bqkv,  g_bqkv);
    cudaGetSymbolAddress((void**)&ob,    g_ob);
    cudaGetSymbolAddress((void**)&attn,  g_attn);
    cudaGetSymbolAddress((void**)&xres,  g_xres);
    cudaGetSymbolAddress((void**)&flat,  g_flat);
    cudaGetSymbolAddress((void**)&h1,    g_h1);
    cudaGetSymbolAddress((void**)&w1t,   g_w1t);
    cudaGetSymbolAddress((void**)&w2t,   g_w2t);
    cudaGetSymbolAddress((void**)&wqkvt, g_wqkvt);
    cudaGetSymbolAddress((void**)&wot,   g_wot);

    cudaFuncSetAttribute(tf32_gemm_kernel<0>, cudaFuncAttributeMaxDynamicSharedMemorySize, GEMM_SMEM);
    cudaFuncSetAttribute(tf32_gemm_kernel<1>, cudaFuncAttributeMaxDynamicSharedMemorySize, GEMM_SMEM);
    cudaFuncSetAttribute(tf32_gemm_kernel<2>, cudaFuncAttributeMaxDynamicSharedMemorySize, GEMM_SMEM);

    // launch 0: zero uniq + concat QKV bias
    zero_kernel<<<4096, 256>>>(uniq, Bv * Mv * Rv, bqkv, bq, bk, bv);
    // launch 1: LN1 + segment-mean scatter
    ln1_scatter_kernel<<<ROWSv, 128>>>(x, ln1w, ln1b);
    // launch 2: round uniq in place (feeds QKV GEMM)
    tf32_round_kernel<<<2048, 256>>>(uniq, uniq, Bv * Mv * Rv);
    // launch 3: fused transpose+round of wq|wk|wv -> wqkvt [1152][384]
    transpose_qkv_kernel<<<dim3(Rv / 32, Rv / 32, 3), dim3(32, 8)>>>(wqkvt, wq, wk, wv);
    // launch 4: transpose w1 (needed later; placed here so launch 5 = QKV GEMM for ncu)
    transpose_tf32_kernel<<<dim3(HIDv / 32, NEv / 32), dim3(32, 8)>>>(w1t, w1, NEv, HIDv);
    // launch 5 (ncu -s 5 target): fused QKV projection (10920 x 1152) = uniq @ wqkvt^T
    tf32_gemm_kernel<0><<<dim3(QKVN / BNt, (BMv + BMt - 1) / BMt), 256, GEMM_SMEM>>>(
        BMv, QKVN, Rv, uniq, wqkvt, bqkv, nullptr, qkv);
    // launch 6: attention over the 1365 tree nodes (reads fused qkv, writes rounded ob)
    attn_kernel<<<dim3((Mv + 127) / 128, NHv, Bv), 128>>>();
    // launch 7: transpose wo
    transpose_tf32_kernel<<<dim3(Rv / 32, Rv / 32), dim3(32, 8)>>>(wot, wo, Rv, Rv);
    // launch 8: output projection
    tf32_gemm_kernel<0><<<dim3(Rv / BNt, (BMv + BMt - 1) / BMt), 256, GEMM_SMEM>>>(
        BMv, Rv, Rv, ob, wot, bo, nullptr, attn);
    // launch 9: gather + residual + LN2 (stores tf32-rounded flat)
    res_ln2_kernel<<<ROWSv, 128>>>(x, ln2w, ln2b);
    // launch 10: transpose w2
    transpose_tf32_kernel<<<dim3(NEv / 32, HIDv / 32), dim3(32, 8)>>>(w2t, w2, HIDv, NEv);
    // launch 11: MLP GEMM1 + GELU: (8192 x 9216) = flat @ w1t^T
    tf32_gemm_kernel<1><<<dim3(HIDv / BNt, MLPROWS / BMt), 256, GEMM_SMEM>>>(
        MLPROWS, HIDv, NEv, flat, w1t, b1, nullptr, h1);
    // launch 12: MLP GEMM2 + bias + residual -> d_out: (8192 x 2304) = h1 @ w2t^T
    tf32_gemm_kernel<2><<<dim3(NEv / BNt, MLPROWS / BMt), 256, GEMM_SMEM>>>(
        MLPROWS, NEv, HIDv, h1, w2t, b2, xres, out);
}

// round 15
// speedup vs baseline: 1.0253x; 1.0004x over previous
#include <cuda_runtime.h>
#include <math.h>
#include <stdint.h>

#define Bv   8
#define Hv   32
#define Wv   32
#define Lv   6
#define Rv   384
#define NHv  6
#define DHv  64
#define Mv   1365
#define NEv  2304
#define HIDv 9216
#define QKVN 1152               /* fused QKV output width */
#define ROWSv (Bv*Hv*Wv*Lv)     /* 49152 */
#define BMv   (Bv*Mv)           /* 10920 */
#define MLPROWS (Bv*Hv*Wv)      /* 8192 */

// ---------------- scratch (static device globals; no allocation) ----------------
__device__ float g_uniq[Bv*Mv*Rv];
__device__ float g_qkv [(size_t)BMv*QKVN];   // fused Q|K|V, row stride 1152
__device__ float g_bqkv[QKVN];               // concat bias bq|bk|bv
__device__ float g_ob  [Bv*Mv*Rv];
__device__ float g_attn[Bv*Mv*Rv];
__device__ float g_xres[ROWSv*Rv];
__device__ float g_flat[ROWSv*Rv];
__device__ float g_h1  [(size_t)MLPROWS*HIDv];
__device__ float g_w1t [(size_t)NEv*HIDv];   // transposed [HID][NE]
__device__ float g_w2t [(size_t)NEv*HIDv];   // transposed [NE][HID]
__device__ float g_wqkvt[QKVN*Rv];           // transposed concat [1152][384]
__device__ float g_wot [Rv*Rv];              // transposed [N][K]

__constant__ int c_off[6] = {0, 1024, 1280, 1344, 1360, 1364};

// ---------------- utility ----------------
__device__ __forceinline__ float gelu_tanh(float v) {
    float u = 0.7978845608028654f * (v + 0.044715f * v * v * v);
    return 0.5f * v * (1.f + tanhf(u));
}

__device__ __forceinline__ uint32_t f2tf(float f) {
    uint32_t r;
    asm volatile("cvt.rna.tf32.f32 %0, %1;" : "=r"(r) : "f"(f));
    return r;
}
__device__ __forceinline__ float tfround(float f) { return __uint_as_float(f2tf(f)); }

// fused: blocks 0..431 transpose+round wq|wk|wv -> wqkvt [1152][384];
//        blocks 432..  zero uniq + build concat QKV bias.
#define TQKV_BLOCKS 432
__global__ __launch_bounds__(256) void zero_tqkv_kernel(
    float* __restrict__ uniq, int n,
    float* __restrict__ bqkv, const float* __restrict__ bq,
    const float* __restrict__ bk, const float* __restrict__ bv,
    float* __restrict__ wqkvt, const float* __restrict__ wq,
    const float* __restrict__ wk, const float* __restrict__ wv)
{
    int tid = threadIdx.x;
    if (blockIdx.x < TQKV_BLOCKS) {
        __shared__ float tile[32][33];
        int z   = blockIdx.x / 144;          // 0..2 selects wq/wk/wv
        int rem = blockIdx.x % 144;
        int by = rem / 12, bx = rem % 12;    // 12x12 tiles of 32x32 over 384x384
        const float* src = (z == 0) ? wq : (z == 1) ? wk : wv;
        float* dst = wqkvt + (size_t)z * Rv * Rv;
        int k0 = by * 32, n0 = bx * 32;
        int tx = tid & 31, ty = tid >> 5;    // (32,8) reinterpretation
        #pragma unroll
        for (int i = 0; i < 32; i += 8)
            tile[ty + i][tx] = src[(size_t)(k0 + ty + i) * Rv + n0 + tx];
        __syncthreads();
        #pragma unroll
        for (int i = 0; i < 32; i += 8)
            dst[(size_t)(n0 + ty + i) * Rv + k0 + tx] = tfround(tile[tx][ty + i]);
        return;
    }
    int g0 = (blockIdx.x - TQKV_BLOCKS) * 256 + tid;
    if (g0 < QKVN)
        bqkv[g0] = (g0 < Rv) ? bq[g0] : (g0 < 2 * Rv) ? bk[g0 - Rv] : bv[g0 - 2 * Rv];
    int stride = (gridDim.x - TQKV_BLOCKS) * 256;
    for (int i = g0; i < n; i += stride) uniq[i] = 0.f;
}

__device__ __forceinline__ void cp_async16(uint32_t dst, const void* src, int sz) {
    asm volatile("cp.async.cg.shared.global [%0], [%1], 16, %2;\n"
                 :: "r"(dst), "l"(src), "r"(sz));
}
__device__ __forceinline__ void cp_commit() {
    asm volatile("cp.async.commit_group;\n");
}

__device__ __forceinline__ void ldsm4(uint32_t& r0, uint32_t& r1, uint32_t& r2, uint32_t& r3,
                                      uint32_t addr) {
    asm volatile("ldmatrix.sync.aligned.m8n8.x4.shared.b16 {%0,%1,%2,%3}, [%4];"
                 : "=r"(r0), "=r"(r1), "=r"(r2), "=r"(r3) : "r"(addr));
}

// elementwise tf32 rounding (vectorized, grid-stride). n % 4 == 0.
__global__ void tf32_round_kernel(float* __restrict__ dst, const float* __restrict__ src, int n) {
    int i = (blockIdx.x * blockDim.x + threadIdx.x) * 4;
    int stride = gridDim.x * blockDim.x * 4;
    for (; i < n; i += stride) {
        float4 v = *(const float4*)(src + i);
        v.x = tfround(v.x); v.y = tfround(v.y);
        v.z = tfround(v.z); v.w = tfround(v.w);
        *(float4*)(dst + i) = v;
    }
}

// transpose + tf32 round: src[K][N] -> dst[N][K]. K,N % 32 == 0. block (32,8).
__global__ __launch_bounds__(256) void transpose_tf32_kernel(
    float* __restrict__ dst, const float* __restrict__ src, int K, int N)
{
    __shared__ float tile[32][33];
    int k0 = blockIdx.y * 32, n0 = blockIdx.x * 32;
    int tx = threadIdx.x, ty = threadIdx.y;
    #pragma unroll
    for (int i = 0; i < 32; i += 8)
        tile[ty + i][tx] = src[(size_t)(k0 + ty + i) * N + n0 + tx];
    __syncthreads();
    #pragma unroll
    for (int i = 0; i < 32; i += 8)
        dst[(size_t)(n0 + ty + i) * K + k0 + tx] = tfround(tile[tx][ty + i]);
}

// ---------------- kernel 1: LN1 + segment-mean scatter into uniq ----------------
__global__ __launch_bounds__(128) void ln1_scatter_kernel(
    const float* __restrict__ x, const float* __restrict__ w, const float* __restrict__ bta)
{
    __shared__ float red[4];
    int row = blockIdx.x;
    int tid = threadIdx.x;
    int l = row % Lv;
    int t = row / Lv;
    int wc = t % Wv; t /= Wv;
    int hc = t % Hv;
    int b  = t / Hv;

    const float* xp = x + (size_t)row * Rv;
    float v0 = xp[tid], v1 = xp[tid + 128], v2 = xp[tid + 256];

    float s = v0 + v1 + v2;
    #pragma unroll
    for (int o = 16; o; o >>= 1) s += __shfl_down_sync(0xffffffffu, s, o);
    if ((tid & 31) == 0) red[tid >> 5] = s;
    __syncthreads();
    float mu = (red[0] + red[1] + red[2] + red[3]) * (1.f / Rv);
    __syncthreads();

    float d0 = v0 - mu, d1 = v1 - mu, d2 = v2 - mu;
    float sq = d0 * d0 + d1 * d1 + d2 * d2;
    #pragma unroll
    for (int o = 16; o; o >>= 1) sq += __shfl_down_sync(0xffffffffu, sq, o);
    if ((tid & 31) == 0) red[tid >> 5] = sq;
    __syncthreads();
    float var = (red[0] + red[1] + red[2] + red[3]) * (1.f / Rv);
    float rstd = rsqrtf(var + 1e-5f);

    int id = c_off[l] + (hc >> l) * (Wv >> l) + (wc >> l);
    float invc = 1.f / (float)(1 << (2 * l));
    float* up = g_uniq + ((size_t)b * Mv + id) * Rv;

    atomicAdd(up + tid,       (d0 * rstd * w[tid]       + bta[tid])       * invc);
    atomicAdd(up + tid + 128, (d1 * rstd * w[tid + 128] + bta[tid + 128]) * invc);
    atomicAdd(up + tid + 256, (d2 * rstd * w[tid + 256] + bta[tid + 256]) * invc);
}

// ---------------- kernel 2: TF32 mma.sync GEMM (R6 champion config) --------------
// C(MxN) = A(MxK) @ Bt^T + bias, Bt layout [N][K], operands pre-rounded tf32.
// EPI 0: bias. EPI 1: gelu(bias+), tf32-rounded out. EPI 2: bias + residual.
// Block tile 128x128, K-tile 32, 3-stage cp.async, smem 110.6KB -> 2 CTAs/SM.
// 8 warps (grid 2x4), warp tile 64x32, mma.m16n8k8 tf32, 4x4 tiles/warp.
// Requires: N % 128 == 0, K % 32 == 0. M arbitrary (guarded).
#define BMt 128
#define BNt 128
#define ASTRIDE 36               /* floats per A smem row (conflict-free LDSM) */
#define BSTN    36               /* floats per Bt smem row */
#define ASZ (BMt*ASTRIDE)        /* 4608 floats */
#define BSZ (BNt*BSTN)           /* 4608 floats */
#define STG (ASZ+BSZ)            /* 9216 floats per stage */
#define NSTAGE 3
#define GEMM_SMEM (NSTAGE*STG*4) /* 110592 bytes */

template<int EPI>
__global__ __launch_bounds__(256, 2) void tf32_gemm_kernel(
    int Mx, int Nx, int Kx,
    const float* __restrict__ A, const float* __restrict__ Bt,
    const float* __restrict__ bias, const float* __restrict__ res,
    float* __restrict__ C)
{
    extern __shared__ float sm[];

    int tid  = threadIdx.x;
    int lane = tid & 31;
    int warp = tid >> 5;
    int wm = warp >> 2;     // 0..1
    int wn = warp & 3;      // 0..3
    int lr = lane >> 2;     // 0..7
    int lc = lane & 3;      // 0..3

    int rowTile = blockIdx.y * BMt;
    int colTile = blockIdx.x * BNt;

    float acc[4][4][4];
    #pragma unroll
    for (int mt = 0; mt < 4; mt++)
        #pragma unroll
        for (int nt = 0; nt < 4; nt++)
            #pragma unroll
            for (int q = 0; q < 4; q++) acc[mt][nt][q] = 0.f;

    int KT = Kx >> 5;

    auto load_tile = [&](int kt, int st) {
        int k0 = kt << 5;
        float* As = sm + st * STG;
        float* Bs = As + ASZ;
        uint32_t sA = (uint32_t)__cvta_generic_to_shared(As);
        uint32_t sB = (uint32_t)__cvta_generic_to_shared(Bs);
        #pragma unroll
        for (int i = 0; i < 4; i++) {
            int idx = i * 256 + tid;            // 1024 chunks: 128 rows x 8
            int row = idx >> 3, c4 = (idx & 7) << 2;
            int gr = rowTile + row;
            const float* src = A + (size_t)(gr < Mx ? gr : (Mx - 1)) * Kx + k0 + c4;
            cp_async16(sA + (row * ASTRIDE + c4) * 4, src, gr < Mx ? 16 : 0);
        }
        #pragma unroll
        for (int i = 0; i < 4; i++) {
            int idx = i * 256 + tid;            // 1024 chunks: 128 n-rows x 8
            int row = idx >> 3, c4 = (idx & 7) << 2;
            cp_async16(sB + (row * BSTN + c4) * 4,
                       Bt + (size_t)(colTile + row) * Kx + k0 + c4, 16);
        }
        cp_commit();
    };

    load_tile(0, 0);
    if (KT > 1) load_tile(1, 1);

    // lane-dependent LDSM address components
    uint32_t aLane = ((wm * 64 + (lane & 15)) * ASTRIDE + ((lane & 16) ? 4 : 0)) * 4;
    uint32_t bLane = ((wn * 32 + (lane & 7) + ((lane & 16) ? 8 : 0)) * BSTN
                     + ((lane & 8) ? 4 : 0)) * 4;

    for (int kt = 0; kt < KT; kt++) {
        if (kt + 1 < KT) asm volatile("cp.async.wait_group 1;\n");
        else             asm volatile("cp.async.wait_group 0;\n");
        __syncthreads();
        if (kt + 2 < KT) load_tile(kt + 2, (kt + 2) % NSTAGE);

        const float* Ab = sm + (kt % NSTAGE) * STG;
        uint32_t aBase = (uint32_t)__cvta_generic_to_shared(Ab) + aLane;
        uint32_t bBase = (uint32_t)__cvta_generic_to_shared(Ab + ASZ) + bLane;

        #pragma unroll
        for (int kk = 0; kk < 4; kk++) {
            uint32_t af[4][4];
            uint32_t bf[4][2];
            #pragma unroll
            for (int mt = 0; mt < 4; mt++)
                ldsm4(af[mt][0], af[mt][1], af[mt][2], af[mt][3],
                      aBase + (mt * 16 * ASTRIDE + kk * 8) * 4);
            #pragma unroll
            for (int np = 0; np < 2; np++)
                ldsm4(bf[2 * np][0], bf[2 * np][1], bf[2 * np + 1][0], bf[2 * np + 1][1],
                      bBase + (np * 16 * BSTN + kk * 8) * 4);
            #pragma unroll
            for (int mt = 0; mt < 4; mt++)
                #pragma unroll
                for (int nt = 0; nt < 4; nt++) {
                    asm volatile(
                        "mma.sync.aligned.m16n8k8.row.col.f32.tf32.tf32.f32 "
                        "{%0,%1,%2,%3}, {%4,%5,%6,%7}, {%8,%9}, {%0,%1,%2,%3};\n"
                        : "+f"(acc[mt][nt][0]), "+f"(acc[mt][nt][1]),
                          "+f"(acc[mt][nt][2]), "+f"(acc[mt][nt][3])
                        : "r"(af[mt][0]), "r"(af[mt][1]), "r"(af[mt][2]), "r"(af[mt][3]),
                          "r"(bf[nt][0]), "r"(bf[nt][1]));
                }
        }
    }

    // ---- epilogue ----
    #pragma unroll
    for (int mt = 0; mt < 4; mt++) {
        #pragma unroll
        for (int nt = 0; nt < 4; nt++) {
            int r0 = rowTile + wm * 64 + mt * 16 + lr;
            int c0 = colTile + wn * 32 + nt * 8 + 2 * lc;
            #pragma unroll
            for (int q = 0; q < 4; q++) {
                int r = r0 + (q >> 1) * 8;
                int c = c0 + (q & 1);
                if (r < Mx) {
                    float val = acc[mt][nt][q] + bias[c];
                    if (EPI == 1) val = tfround(gelu_tanh(val));
                    if (EPI == 2) val += res[(size_t)r * Nx + c];
                    C[(size_t)r * Nx + c] = val;
                }
            }
        }
    }
}

// ---------------- kernel 3: attention over M=1365 nodes, flash-style ------------
// reads fused g_qkv: Q at +0, K at +384, V at +768 within each 1152-float row
#define AKT 64
__global__ __launch_bounds__(128) void attn_kernel()
{
    __shared__ float Ks[AKT][DHv];
    __shared__ float Vs[AKT][DHv];
    int b = blockIdx.z, h = blockIdx.y;
    int qm = blockIdx.x * 128 + threadIdx.x;
    bool valid = qm < Mv;
    int qsafe = valid ? qm : 0;

    const float* qptr = g_qkv + (size_t)(b * Mv + qsafe) * QKVN + h * DHv;
    float q[DHv];
    #pragma unroll
    for (int d = 0; d < DHv; d += 4) {
        float4 t = *(const float4*)(qptr + d);
        q[d] = t.x; q[d + 1] = t.y; q[d + 2] = t.z; q[d + 3] = t.w;
    }
    float o[DHv];
    #pragma unroll
    for (int d = 0; d < DHv; d++) o[d] = 0.f;
    float mmax = -1e30f, lsum = 0.f;

    for (int k0 = 0; k0 < Mv; k0 += AKT) {
        int nk = min(AKT, Mv - k0);
        __syncthreads();
        for (int idx = threadIdx.x; idx < AKT * (DHv / 4); idx += 128) {
            int j = idx >> 4, dq = (idx & 15) * 4;
            if (j < nk) {
                size_t rowb = (size_t)(b * Mv + k0 + j) * QKVN + h * DHv + dq;
                *(float4*)&Ks[j][dq] = *(const float4*)(g_qkv + rowb + Rv);
                *(float4*)&Vs[j][dq] = *(const float4*)(g_qkv + rowb + 2 * Rv);
            }
        }
        __syncthreads();
        if (valid) {
            for (int j = 0; j < nk; j++) {
                const float4* kp = (const float4*)&Ks[j][0];
                float dot = 0.f;
                #pragma unroll
                for (int d4 = 0; d4 < DHv / 4; d4++) {
                    float4 kv = kp[d4];
                    dot = fmaf(q[4 * d4],     kv.x, dot);
                    dot = fmaf(q[4 * d4 + 1], kv.y, dot);
                    dot = fmaf(q[4 * d4 + 2], kv.z, dot);
                    dot = fmaf(q[4 * d4 + 3], kv.w, dot);
                }
                float s = dot * 0.125f;
                const float4* vp = (const float4*)&Vs[j][0];
                if (s <= mmax) {
                    float p = __expf(s - mmax);
                    lsum += p;
                    #pragma unroll
                    for (int d4 = 0; d4 < DHv / 4; d4++) {
                        float4 vv = vp[d4];
                        o[4 * d4]     = fmaf(p, vv.x, o[4 * d4]);
                        o[4 * d4 + 1] = fmaf(p, vv.y, o[4 * d4 + 1]);
                        o[4 * d4 + 2] = fmaf(p, vv.z, o[4 * d4 + 2]);
                        o[4 * d4 + 3] = fmaf(p, vv.w, o[4 * d4 + 3]);
                    }
                } else {
                    float alpha = __expf(mmax - s);
                    mmax = s;
                    lsum = lsum * alpha + 1.f;
                    #pragma unroll
                    for (int d4 = 0; d4 < DHv / 4; d4++) {
                        float4 vv = vp[d4];
                        o[4 * d4]     = fmaf(o[4 * d4],     alpha, vv.x);
                        o[4 * d4 + 1] = fmaf(o[4 * d4 + 1], alpha, vv.y);
                        o[4 * d4 + 2] = fmaf(o[4 * d4 + 2], alpha, vv.z);
                        o[4 * d4 + 3] = fmaf(o[4 * d4 + 3], alpha, vv.w);
                    }
                }
            }
        }
    }
    if (valid) {
        float inv = 1.f / lsum;
        float* op = g_ob + (size_t)(b * Mv + qm) * Rv + h * DHv;
        #pragma unroll
        for (int d = 0; d < DHv; d += 4) {
            float4 t = make_float4(tfround(o[d] * inv), tfround(o[d + 1] * inv),
                                   tfround(o[d + 2] * inv), tfround(o[d + 3] * inv));
            *(float4*)(op + d) = t;
        }
    }
}

// ---------------- kernel 4: gather + residual + LN2 -> x_res, flat --------------
__global__ __launch_bounds__(128) void res_ln2_kernel(
    const float* __restrict__ x, const float* __restrict__ w, const float* __restrict__ bta)
{
    __shared__ float red[4];
    int row = blockIdx.x;
    int tid = threadIdx.x;
    int l = row % Lv;
    int t = row / Lv;
    int wc = t % Wv; t /= Wv;
    int hc = t % Hv;
    int b  = t / Hv;

    int id = c_off[l] + (hc >> l) * (Wv >> l) + (wc >> l);
    const float* xp = x + (size_t)row * Rv;
    const float* ap = g_attn + ((size_t)b * Mv + id) * Rv;

    float v0 = xp[tid]       + ap[tid];
    float v1 = xp[tid + 128] + ap[tid + 128];
    float v2 = xp[tid + 256] + ap[tid + 256];

    float* rp = g_xres + (size_t)row * Rv;
    rp[tid] = v0; rp[tid + 128] = v1; rp[tid + 256] = v2;

    float s = v0 + v1 + v2;
    #pragma unroll
    for (int o = 16; o; o >>= 1) s += __shfl_down_sync(0xffffffffu, s, o);
    if ((tid & 31) == 0) red[tid >> 5] = s;
    __syncthreads();
    float mu = (red[0] + red[1] + red[2] + red[3]) * (1.f / Rv);
    __syncthreads();

    float d0 = v0 - mu, d1 = v1 - mu, d2 = v2 - mu;
    float sq = d0 * d0 + d1 * d1 + d2 * d2;
    #pragma unroll
    for (int o = 16; o; o >>= 1) sq += __shfl_down_sync(0xffffffffu, sq, o);
    if ((tid & 31) == 0) red[tid >> 5] = sq;
    __syncthreads();
    float var = (red[0] + red[1] + red[2] + red[3]) * (1.f / Rv);
    float rstd = rsqrtf(var + 1e-5f);

    float* fp = g_flat + (size_t)row * Rv;  // tf32-rounded: feeds MLP GEMM1
    fp[tid]       = tfround(d0 * rstd * w[tid]       + bta[tid]);
    fp[tid + 128] = tfround(d1 * rstd * w[tid + 128] + bta[tid + 128]);
    fp[tid + 256] = tfround(d2 * rstd * w[tid + 256] + bta[tid + 256]);
}

// ---------------- launch ----------------
extern "C" void kernel_launch(void* const* d_in, const int* in_sizes, int n_in,
                              void* d_out, int out_size) {
    const float* x    = (const float*)d_in[0];
    const float* ln1w = (const float*)d_in[1];
    const float* ln1b = (const float*)d_in[2];
    const float* ln2w = (const float*)d_in[3];
    const float* ln2b = (const float*)d_in[4];
    const float* wq = (const float*)d_in[5];  const float* bq = (const float*)d_in[6];
    const float* wk = (const float*)d_in[7];  const float* bk = (const float*)d_in[8];
    const float* wv = (const float*)d_in[9];  const float* bv = (const float*)d_in[10];
    const float* wo = (const float*)d_in[11]; const float* bo = (const float*)d_in[12];
    const float* w1 = (const float*)d_in[13]; const float* b1 = (const float*)d_in[14];
    const float* w2 = (const float*)d_in[15]; const float* b2 = (const float*)d_in[16];
    float* out = (float*)d_out;

    float *uniq, *qkv, *bqkv, *ob, *attn, *xres, *flat, *h1;
    float *w1t, *w2t, *wqkvt, *wot;
    cudaGetSymbolAddress((void**)&uniq,  g_uniq);
    cudaGetSymbolAddress((void**)&qkv,   g_qkv);
    cudaGetSymbolAddress((void**)&bqkv,  g_bqkv);
    cudaGetSymbolAddress((void**)&ob,    g_ob);
    cudaGetSymbolAddress((void**)&attn,  g_attn);
    cudaGetSymbolAddress((void**)&xres,  g_xres);
    cudaGetSymbolAddress((void**)&flat,  g_flat);
    cudaGetSymbolAddress((void**)&h1,    g_h1);
    cudaGetSymbolAddress((void**)&w1t,   g_w1t);
    cudaGetSymbolAddress((void**)&w2t,   g_w2t);
    cudaGetSymbolAddress((void**)&wqkvt, g_wqkvt);
    cudaGetSymbolAddress((void**)&wot,   g_wot);

    cudaFuncSetAttribute(tf32_gemm_kernel<0>, cudaFuncAttributeMaxDynamicSharedMemorySize, GEMM_SMEM);
    cudaFuncSetAttribute(tf32_gemm_kernel<1>, cudaFuncAttributeMaxDynamicSharedMemorySize, GEMM_SMEM);
    cudaFuncSetAttribute(tf32_gemm_kernel<2>, cudaFuncAttributeMaxDynamicSharedMemorySize, GEMM_SMEM);

    // launch 0: fused [qkv weight transpose+round] + [zero uniq + concat bias]
    zero_tqkv_kernel<<<4096 + TQKV_BLOCKS, 256>>>(uniq, Bv * Mv * Rv,
                                                  bqkv, bq, bk, bv,
                                                  wqkvt, wq, wk, wv);
    // launch 1: LN1 + segment-mean scatter
    ln1_scatter_kernel<<<ROWSv, 128>>>(x, ln1w, ln1b);
    // launch 2: round uniq in place (feeds QKV GEMM)
    tf32_round_kernel<<<2048, 256>>>(uniq, uniq, Bv * Mv * Rv);
    // launch 3 (ncu capture target): fused QKV projection (10920 x 1152)
    tf32_gemm_kernel<0><<<dim3(QKVN / BNt, (BMv + BMt - 1) / BMt), 256, GEMM_SMEM>>>(
        BMv, QKVN, Rv, uniq, wqkvt, bqkv, nullptr, qkv);
    // launch 4: attention over the 1365 tree nodes (reads fused qkv, writes rounded ob)
    attn_kernel<<<dim3((Mv + 127) / 128, NHv, Bv), 128>>>();
    // launch 5: transpose wo
    transpose_tf32_kernel<<<dim3(Rv / 32, Rv / 32), dim3(32, 8)>>>(wot, wo, Rv, Rv);
    // launch 6: output projection
    tf32_gemm_kernel<0><<<dim3(Rv / BNt, (BMv + BMt - 1) / BMt), 256, GEMM_SMEM>>>(
        BMv, Rv, Rv, ob, wot, bo, nullptr, attn);
    // launch 7: gather + residual + LN2 (stores tf32-rounded flat)
    res_ln2_kernel<<<ROWSv, 128>>>(x, ln2w, ln2b);
    // launch 8: transpose w1
    transpose_tf32_kernel<<<dim3(HIDv / 32, NEv / 32), dim3(32, 8)>>>(w1t, w1, NEv, HIDv);
    // launch 9: MLP GEMM1 + GELU: (8192 x 9216) = flat @ w1t^T
    tf32_gemm_kernel<1><<<dim3(HIDv / BNt, MLPROWS / BMt), 256, GEMM_SMEM>>>(
        MLPROWS, HIDv, NEv, flat, w1t, b1, nullptr, h1);
    // launch 10: transpose w2
    transpose_tf32_kernel<<<dim3(NEv / 32, HIDv / 32), dim3(32, 8)>>>(w2t, w2, HIDv, NEv);
    // launch 11: MLP GEMM2 + bias + residual -> d_out: (8192 x 2304) = h1 @ w2t^T
    tf32_gemm_kernel<2><<<dim3(NEv / BNt, MLPROWS / BMt), 256, GEMM_SMEM>>>(
        MLPROWS, NEv, HIDv, h1, w2t, b2, xres, out);
}